// round 13
// baseline (speedup 1.0000x reference)
#include <cuda_runtime.h>
#include <math.h>

#define N_ROWS 8000
#define D_DIM  9
#define K1_T   128                            // threads per block
#define K1_B   ((N_ROWS + K1_T - 1) / K1_T)   // 63 blocks
#define SCAN_PER_T 63                         // 128 * 63 = 8064 >= 8000

// Scratch: device globals (no allocation allowed anywhere)
__device__ float g_sdiff[N_ROWS];  // s2 - s1
__device__ float g_df[N_ROWS];     // (f1+b1) - (f2+b2)
__device__ float g_f2[N_ROWS];     // f2 + b2
__device__ float g_wbar[N_ROWS];   // sigmoid(cumsum(sdiff))
__device__ int   g_ctr = 0;        // last-block-done counter (self-resetting)

// ---------------------------------------------------------------------------
// Fused k1+k2: per-row stats across 63 blocks (direct __ldg loads — the
// proven-fastest k1 shape), then the LAST block to finish runs the 8000-elem
// inclusive scan + sigmoid on L2-hot g_sdiff. Saves one launch + gap + reload.
// ---------------------------------------------------------------------------
__global__ void __launch_bounds__(K1_T) k_stats_scan(
    const float* __restrict__ x,
    const float* __restrict__ a1p, const float* __restrict__ c1p,
    const float* __restrict__ a2p, const float* __restrict__ c2p,
    const float* __restrict__ w1,  const float* __restrict__ b1,
    const float* __restrict__ w2,  const float* __restrict__ b2)
{
    const int tid = threadIdx.x;
    const int i   = blockIdx.x * K1_T + tid;

    // ---- Phase 1: row stats (one thread = one row, 9 direct loads) ----
    if (i < N_ROWS) {
        const float a1 = a1p[0], c1 = c1p[0], a2 = a2p[0], c2 = c2p[0];
        const float inv_a1 = 1.0f / a1, inv_a2 = 1.0f / a2;

        const float* xr = x + (size_t)i * D_DIM;
        float s1 = 0.f, s2 = 0.f, f1 = 0.f, f2 = 0.f;
#pragma unroll
        for (int d = 0; d < D_DIM; d++) {
            float xv = __ldg(xr + d);
            float t1 = (xv - c1) * inv_a1;
            float t2 = (xv - c2) * inv_a2;
            s1 = fmaf(t1, t1, s1);
            s2 = fmaf(t2, t2, s2);
            f1 = fmaf(xv, w1[d], f1);
            f2 = fmaf(xv, w2[d], f2);
        }
        g_sdiff[i] = s2 - s1;
        float f2b = f2 + b2[0];
        g_f2[i] = f2b;
        g_df[i] = (f1 + b1[0]) - f2b;
    }

    // ---- Elect the last-finishing block ----
    __shared__ bool s_last;
    __threadfence();              // publish this block's global stores
    __syncthreads();
    if (tid == 0) {
        int old = atomicAdd(&g_ctr, 1);
        s_last = (old == K1_B - 1);
        if (s_last) atomicExch(&g_ctr, 0);   // reset for next graph replay
    }
    __syncthreads();
    if (!s_last) return;
    __threadfence();              // acquire: observe all blocks' g_sdiff

    // ---- Phase 2 (last block only): inclusive scan + sigmoid ----
    __shared__ float s_warp[32];
    const int lane = tid & 31;
    const int wid  = tid >> 5;

    const int base = tid * SCAN_PER_T;
    const int lo   = min(base, N_ROWS);
    const int hi   = min(base + SCAN_PER_T, N_ROWS);

    // pass 1: per-thread total (independent loads, pipelined; L2-hit)
    float tot = 0.f;
    for (int k = lo; k < hi; k++) tot += g_sdiff[k];

    // warp-inclusive scan of thread totals
    float ws = tot;
#pragma unroll
    for (int off = 1; off < 32; off <<= 1) {
        float t = __shfl_up_sync(0xFFFFFFFFu, ws, off);
        if (lane >= off) ws += t;
    }
    if (lane == 31) s_warp[wid] = ws;
    __syncthreads();
    if (wid == 0) {
        float w = (lane < K1_T / 32) ? s_warp[lane] : 0.f;
#pragma unroll
        for (int off = 1; off < 32; off <<= 1) {
            float t = __shfl_up_sync(0xFFFFFFFFu, w, off);
            if (lane >= off) w += t;
        }
        if (lane < K1_T / 32) s_warp[lane] = w;
    }
    __syncthreads();

    float prefix = ((wid > 0) ? s_warp[wid - 1] : 0.f) + (ws - tot);

    // pass 2: running prefix + sigmoid
    for (int k = lo; k < hi; k++) {
        prefix += g_sdiff[k];
        g_wbar[k] = 1.0f / (1.0f + expf(-prefix));
    }
}

// ---------------------------------------------------------------------------
// K3: out[i, j] = f2[i] + df[i] * wbar[j]
// Two rows per block (proven best: regs=28, occ=79%), streaming stores.
// UNCHANGED from R9.
// ---------------------------------------------------------------------------
__global__ void __launch_bounds__(256) k3_outer(float* __restrict__ out)
{
    const int rowA = blockIdx.x * 2;
    const int rowB = rowA + 1;

    const float f2A = g_f2[rowA];
    const float dfA = g_df[rowA];
    const float f2B = g_f2[rowB];
    const float dfB = g_df[rowB];

    const float4* __restrict__ wb4 = (const float4*)g_wbar;
    float4* __restrict__ oA = (float4*)(out + (size_t)rowA * N_ROWS);
    float4* __restrict__ oB = (float4*)(out + (size_t)rowB * N_ROWS);

#pragma unroll 4
    for (int j = threadIdx.x; j < N_ROWS / 4; j += 256) {
        float4 w = wb4[j];
        float4 rA, rB;
        rA.x = fmaf(dfA, w.x, f2A); rA.y = fmaf(dfA, w.y, f2A);
        rA.z = fmaf(dfA, w.z, f2A); rA.w = fmaf(dfA, w.w, f2A);
        rB.x = fmaf(dfB, w.x, f2B); rB.y = fmaf(dfB, w.y, f2B);
        rB.z = fmaf(dfB, w.z, f2B); rB.w = fmaf(dfB, w.w, f2B);
        __stcs(&oA[j], rA);
        __stcs(&oB[j], rB);
    }
}

// ---------------------------------------------------------------------------
extern "C" void kernel_launch(void* const* d_in, const int* in_sizes, int n_in,
                              void* d_out, int out_size)
{
    const float* x     = (const float*)d_in[0];
    const float* a1    = (const float*)d_in[1];
    const float* c1    = (const float*)d_in[2];
    const float* a2    = (const float*)d_in[3];
    const float* c2    = (const float*)d_in[4];
    const float* w_fc1 = (const float*)d_in[5];
    const float* b_fc1 = (const float*)d_in[6];
    const float* w_fc2 = (const float*)d_in[7];
    const float* b_fc2 = (const float*)d_in[8];
    float* out = (float*)d_out;

    k_stats_scan<<<K1_B, K1_T>>>(x, a1, c1, a2, c2,
                                 w_fc1, b_fc1, w_fc2, b_fc2);
    k3_outer<<<N_ROWS / 2, 256>>>(out);
}

// round 14
// speedup vs baseline: 1.1342x; 1.1342x over previous
#include <cuda_runtime.h>
#include <math.h>

#define N_ROWS 8000
#define D_DIM  9

// Scratch: device globals (no allocation allowed anywhere)
__device__ float g_sdiff[N_ROWS];  // s2 - s1
__device__ float g_df[N_ROWS];     // (f1+b1) - (f2+b2)
__device__ float g_f2[N_ROWS];     // f2 + b2
__device__ float g_wbar[N_ROWS];   // sigmoid(cumsum(sdiff))

// ---------------------------------------------------------------------------
// K1: per-row stats, one thread = one row, direct __ldg loads.
// (R3-measured 5.6us — faster than the smem-staged variant at 6.9us;
//  kernel is latency-bound at 0.5% DRAM, so coalescing buys nothing.)
// ---------------------------------------------------------------------------
__global__ void __launch_bounds__(128) k1_rowstats(
    const float* __restrict__ x,
    const float* __restrict__ a1p, const float* __restrict__ c1p,
    const float* __restrict__ a2p, const float* __restrict__ c2p,
    const float* __restrict__ w1,  const float* __restrict__ b1,
    const float* __restrict__ w2,  const float* __restrict__ b2)
{
    int i = blockIdx.x * blockDim.x + threadIdx.x;
    if (i >= N_ROWS) return;

    const float a1 = a1p[0], c1 = c1p[0], a2 = a2p[0], c2 = c2p[0];
    const float inv_a1 = 1.0f / a1, inv_a2 = 1.0f / a2;

    const float* xr = x + (size_t)i * D_DIM;
    float s1 = 0.f, s2 = 0.f, f1 = 0.f, f2 = 0.f;
#pragma unroll
    for (int d = 0; d < D_DIM; d++) {
        float xv = __ldg(xr + d);
        float t1 = (xv - c1) * inv_a1;
        float t2 = (xv - c2) * inv_a2;
        s1 = fmaf(t1, t1, s1);
        s2 = fmaf(t2, t2, s2);
        f1 = fmaf(xv, w1[d], f1);
        f2 = fmaf(xv, w2[d], f2);
    }
    g_sdiff[i] = s2 - s1;
    float f2b = f2 + b2[0];
    g_f2[i] = f2b;
    g_df[i] = (f1 + b1[0]) - f2b;
}

// ---------------------------------------------------------------------------
// K2: single-pass inclusive scan of 8000 elems -> wbar = sigmoid(prefix).
// 8000 = 1000 threads x 8 elems exactly; threads 1000..1023 contribute 0.
// UNCHANGED from R9 (proven).
// ---------------------------------------------------------------------------
__global__ void __launch_bounds__(1024) k2_scan_sigmoid()
{
    __shared__ float s_warp[32];

    const int tid  = threadIdx.x;
    const int lane = tid & 31;
    const int wid  = tid >> 5;
    const bool active = (tid < 1000);

    float e[8] = {0.f, 0.f, 0.f, 0.f, 0.f, 0.f, 0.f, 0.f};
    if (active) {
        const float4* __restrict__ in4 = (const float4*)g_sdiff;
        float4 va = in4[2 * tid];
        float4 vb = in4[2 * tid + 1];
        e[0] = va.x; e[1] = va.y; e[2] = va.z; e[3] = va.w;
        e[4] = vb.x; e[5] = vb.y; e[6] = vb.z; e[7] = vb.w;
    }
#pragma unroll
    for (int k = 1; k < 8; k++) e[k] += e[k - 1];
    float tot = e[7];

    float ws = tot;
#pragma unroll
    for (int off = 1; off < 32; off <<= 1) {
        float t = __shfl_up_sync(0xFFFFFFFFu, ws, off);
        if (lane >= off) ws += t;
    }
    if (lane == 31) s_warp[wid] = ws;
    __syncthreads();
    if (wid == 0) {
        float w = s_warp[lane];
#pragma unroll
        for (int off = 1; off < 32; off <<= 1) {
            float t = __shfl_up_sync(0xFFFFFFFFu, w, off);
            if (lane >= off) w += t;
        }
        s_warp[lane] = w;
    }
    __syncthreads();

    float warp_prefix   = (wid > 0) ? s_warp[wid - 1] : 0.f;
    float thread_prefix = warp_prefix + (ws - tot);

    if (active) {
        float o[8];
#pragma unroll
        for (int k = 0; k < 8; k++) {
            float Dv = thread_prefix + e[k];
            o[k] = 1.0f / (1.0f + expf(-Dv));
        }
        float4* __restrict__ out4 = (float4*)g_wbar;
        out4[2 * tid]     = make_float4(o[0], o[1], o[2], o[3]);
        out4[2 * tid + 1] = make_float4(o[4], o[5], o[6], o[7]);
    }
}

// ---------------------------------------------------------------------------
// K3: out[i, j] = f2[i] + df[i] * wbar[j]
// Two rows per block (proven best: regs=28, occ~80%), streaming stores.
// UNCHANGED from R9 (proven).
// ---------------------------------------------------------------------------
__global__ void __launch_bounds__(256) k3_outer(float* __restrict__ out)
{
    const int rowA = blockIdx.x * 2;
    const int rowB = rowA + 1;

    const float f2A = g_f2[rowA];
    const float dfA = g_df[rowA];
    const float f2B = g_f2[rowB];
    const float dfB = g_df[rowB];

    const float4* __restrict__ wb4 = (const float4*)g_wbar;
    float4* __restrict__ oA = (float4*)(out + (size_t)rowA * N_ROWS);
    float4* __restrict__ oB = (float4*)(out + (size_t)rowB * N_ROWS);

#pragma unroll 4
    for (int j = threadIdx.x; j < N_ROWS / 4; j += 256) {
        float4 w = wb4[j];
        float4 rA, rB;
        rA.x = fmaf(dfA, w.x, f2A); rA.y = fmaf(dfA, w.y, f2A);
        rA.z = fmaf(dfA, w.z, f2A); rA.w = fmaf(dfA, w.w, f2A);
        rB.x = fmaf(dfB, w.x, f2B); rB.y = fmaf(dfB, w.y, f2B);
        rB.z = fmaf(dfB, w.z, f2B); rB.w = fmaf(dfB, w.w, f2B);
        __stcs(&oA[j], rA);
        __stcs(&oB[j], rB);
    }
}

// ---------------------------------------------------------------------------
extern "C" void kernel_launch(void* const* d_in, const int* in_sizes, int n_in,
                              void* d_out, int out_size)
{
    const float* x     = (const float*)d_in[0];
    const float* a1    = (const float*)d_in[1];
    const float* c1    = (const float*)d_in[2];
    const float* a2    = (const float*)d_in[3];
    const float* c2    = (const float*)d_in[4];
    const float* w_fc1 = (const float*)d_in[5];
    const float* b_fc1 = (const float*)d_in[6];
    const float* w_fc2 = (const float*)d_in[7];
    const float* b_fc2 = (const float*)d_in[8];
    float* out = (float*)d_out;

    k1_rowstats<<<(N_ROWS + 127) / 128, 128>>>(x, a1, c1, a2, c2,
                                               w_fc1, b_fc1, w_fc2, b_fc2);
    k2_scan_sigmoid<<<1, 1024>>>();
    k3_outer<<<N_ROWS / 2, 256>>>(out);
}

// round 15
// speedup vs baseline: 1.1414x; 1.0063x over previous
#include <cuda_runtime.h>
#include <math.h>

#define N_ROWS 8000
#define D_DIM  9
#define K1_T   32                             // 1 warp per block
#define K1_B   ((N_ROWS + K1_T - 1) / K1_T)   // 250 blocks -> covers all 148 SMs

// Scratch: device globals (no allocation allowed anywhere)
__device__ float g_sdiff[N_ROWS];  // s2 - s1
__device__ float g_df[N_ROWS];     // (f1+b1) - (f2+b2)
__device__ float g_f2[N_ROWS];     // f2 + b2
__device__ float g_wbar[N_ROWS];   // sigmoid(cumsum(sdiff))

// ---------------------------------------------------------------------------
// K1: per-row stats, one thread = one row, direct __ldg loads.
// grid=250 x block=32: spread over ALL 148 SMs (vs 63 with block=128) to
// multiply the independent L1tex/LSU paths — the kernel is pure load latency
// (0.6% DRAM, 3.1% issue), so SM coverage is the binding resource.
// ---------------------------------------------------------------------------
__global__ void __launch_bounds__(K1_T) k1_rowstats(
    const float* __restrict__ x,
    const float* __restrict__ a1p, const float* __restrict__ c1p,
    const float* __restrict__ a2p, const float* __restrict__ c2p,
    const float* __restrict__ w1,  const float* __restrict__ b1,
    const float* __restrict__ w2,  const float* __restrict__ b2)
{
    int i = blockIdx.x * K1_T + threadIdx.x;
    if (i >= N_ROWS) return;

    const float a1 = a1p[0], c1 = c1p[0], a2 = a2p[0], c2 = c2p[0];
    const float inv_a1 = 1.0f / a1, inv_a2 = 1.0f / a2;

    const float* xr = x + (size_t)i * D_DIM;
    float s1 = 0.f, s2 = 0.f, f1 = 0.f, f2 = 0.f;
#pragma unroll
    for (int d = 0; d < D_DIM; d++) {
        float xv = __ldg(xr + d);
        float t1 = (xv - c1) * inv_a1;
        float t2 = (xv - c2) * inv_a2;
        s1 = fmaf(t1, t1, s1);
        s2 = fmaf(t2, t2, s2);
        f1 = fmaf(xv, w1[d], f1);
        f2 = fmaf(xv, w2[d], f2);
    }
    g_sdiff[i] = s2 - s1;
    float f2b = f2 + b2[0];
    g_f2[i] = f2b;
    g_df[i] = (f1 + b1[0]) - f2b;
}

// ---------------------------------------------------------------------------
// K2: single-pass inclusive scan of 8000 elems -> wbar = sigmoid(prefix).
// 8000 = 1000 threads x 8 elems exactly; threads 1000..1023 contribute 0.
// UNCHANGED (proven).
// ---------------------------------------------------------------------------
__global__ void __launch_bounds__(1024) k2_scan_sigmoid()
{
    __shared__ float s_warp[32];

    const int tid  = threadIdx.x;
    const int lane = tid & 31;
    const int wid  = tid >> 5;
    const bool active = (tid < 1000);

    float e[8] = {0.f, 0.f, 0.f, 0.f, 0.f, 0.f, 0.f, 0.f};
    if (active) {
        const float4* __restrict__ in4 = (const float4*)g_sdiff;
        float4 va = in4[2 * tid];
        float4 vb = in4[2 * tid + 1];
        e[0] = va.x; e[1] = va.y; e[2] = va.z; e[3] = va.w;
        e[4] = vb.x; e[5] = vb.y; e[6] = vb.z; e[7] = vb.w;
    }
#pragma unroll
    for (int k = 1; k < 8; k++) e[k] += e[k - 1];
    float tot = e[7];

    float ws = tot;
#pragma unroll
    for (int off = 1; off < 32; off <<= 1) {
        float t = __shfl_up_sync(0xFFFFFFFFu, ws, off);
        if (lane >= off) ws += t;
    }
    if (lane == 31) s_warp[wid] = ws;
    __syncthreads();
    if (wid == 0) {
        float w = s_warp[lane];
#pragma unroll
        for (int off = 1; off < 32; off <<= 1) {
            float t = __shfl_up_sync(0xFFFFFFFFu, w, off);
            if (lane >= off) w += t;
        }
        s_warp[lane] = w;
    }
    __syncthreads();

    float warp_prefix   = (wid > 0) ? s_warp[wid - 1] : 0.f;
    float thread_prefix = warp_prefix + (ws - tot);

    if (active) {
        float o[8];
#pragma unroll
        for (int k = 0; k < 8; k++) {
            float Dv = thread_prefix + e[k];
            o[k] = 1.0f / (1.0f + expf(-Dv));
        }
        float4* __restrict__ out4 = (float4*)g_wbar;
        out4[2 * tid]     = make_float4(o[0], o[1], o[2], o[3]);
        out4[2 * tid + 1] = make_float4(o[4], o[5], o[6], o[7]);
    }
}

// ---------------------------------------------------------------------------
// K3: out[i, j] = f2[i] + df[i] * wbar[j]
// Two rows per block (proven best: regs=28, occ~80%), streaming stores.
// UNCHANGED (proven).
// ---------------------------------------------------------------------------
__global__ void __launch_bounds__(256) k3_outer(float* __restrict__ out)
{
    const int rowA = blockIdx.x * 2;
    const int rowB = rowA + 1;

    const float f2A = g_f2[rowA];
    const float dfA = g_df[rowA];
    const float f2B = g_f2[rowB];
    const float dfB = g_df[rowB];

    const float4* __restrict__ wb4 = (const float4*)g_wbar;
    float4* __restrict__ oA = (float4*)(out + (size_t)rowA * N_ROWS);
    float4* __restrict__ oB = (float4*)(out + (size_t)rowB * N_ROWS);

#pragma unroll 4
    for (int j = threadIdx.x; j < N_ROWS / 4; j += 256) {
        float4 w = wb4[j];
        float4 rA, rB;
        rA.x = fmaf(dfA, w.x, f2A); rA.y = fmaf(dfA, w.y, f2A);
        rA.z = fmaf(dfA, w.z, f2A); rA.w = fmaf(dfA, w.w, f2A);
        rB.x = fmaf(dfB, w.x, f2B); rB.y = fmaf(dfB, w.y, f2B);
        rB.z = fmaf(dfB, w.z, f2B); rB.w = fmaf(dfB, w.w, f2B);
        __stcs(&oA[j], rA);
        __stcs(&oB[j], rB);
    }
}

// ---------------------------------------------------------------------------
extern "C" void kernel_launch(void* const* d_in, const int* in_sizes, int n_in,
                              void* d_out, int out_size)
{
    const float* x     = (const float*)d_in[0];
    const float* a1    = (const float*)d_in[1];
    const float* c1    = (const float*)d_in[2];
    const float* a2    = (const float*)d_in[3];
    const float* c2    = (const float*)d_in[4];
    const float* w_fc1 = (const float*)d_in[5];
    const float* b_fc1 = (const float*)d_in[6];
    const float* w_fc2 = (const float*)d_in[7];
    const float* b_fc2 = (const float*)d_in[8];
    float* out = (float*)d_out;

    k1_rowstats<<<K1_B, K1_T>>>(x, a1, c1, a2, c2,
                                w_fc1, b_fc1, w_fc2, b_fc2);
    k2_scan_sigmoid<<<1, 1024>>>();
    k3_outer<<<N_ROWS / 2, 256>>>(out);
}